// round 6
// baseline (speedup 1.0000x reference)
#include <cuda_runtime.h>
#include <cuda_fp16.h>

// SDFGrid: trilinear-interpolated grid normals + relu(-grid) gather.
//
// R6: revert precompute to R4's brick-per-thread form (R5's 16-node version
// blew register pressure and regressed), with __stcs on table stores so the
// streaming table writes don't evict the L2-resident grid. Gather keeps R5's
// streaming hints.

#define GRID_R   256
#define NVOX     (GRID_R * GRID_R * GRID_R)

// Brick-swizzled: node (x,y,z) -> uint2 index
//   brick = ((x>>1)*128 + (y>>1))*128 + (z>>1)
//   idx   = brick*8 + (x&1)*4 + (y&1)*2 + (z&1)
static __device__ uint2 g_table[NVOX];

__device__ __forceinline__ unsigned int packh2(float a, float b) {
    __half2 h = __floats2half2_rn(a, b);
    return *reinterpret_cast<unsigned int*>(&h);
}

// float2 index of the z-pair (bz) of row (x, y)
__device__ __forceinline__ int rowf2(int x, int y, int bz) {
    return ((x << 8) + y) * 128 + bz;
}

// One thread = one 2x2x2 brick (8 nodes), 4 contiguous 16B streaming stores.
__global__ void __launch_bounds__(256)
precompute_normals_kernel(const float* __restrict__ g) {
    int tid = blockIdx.x * blockDim.x + threadIdx.x;   // NVOX/8 threads
    int bz = tid & 127;
    int by = (tid >> 7) & 127;
    int bx = tid >> 14;

    int x0 = bx << 1, x1 = x0 + 1;
    int y0 = by << 1, y1 = y0 + 1;

    const float2* __restrict__ g2 = (const float2*)g;

    float2 c00 = __ldg(g2 + rowf2(x0, y0, bz));
    float2 c01 = __ldg(g2 + rowf2(x0, y1, bz));
    float2 c10 = __ldg(g2 + rowf2(x1, y0, bz));
    float2 c11 = __ldg(g2 + rowf2(x1, y1, bz));

    // ---- z neighbors: scalars at z0-1, z0+2 (clamped addr at borders) ----
    bool zlo = (bz == 0), zhi = (bz == 127);
    int dm = zlo ? 0 : -1;
    int dp = zhi ? 0 : 2;
    int e00 = rowf2(x0, y0, bz) * 2, e01 = rowf2(x0, y1, bz) * 2;
    int e10 = rowf2(x1, y0, bz) * 2, e11 = rowf2(x1, y1, bz) * 2;
    float zm00 = __ldg(g + e00 + dm), zp00 = __ldg(g + e00 + dp);
    float zm01 = __ldg(g + e01 + dm), zp01 = __ldg(g + e01 + dp);
    float zm10 = __ldg(g + e10 + dm), zp10 = __ldg(g + e10 + dp);
    float zm11 = __ldg(g + e11 + dm), zp11 = __ldg(g + e11 + dp);

#define DZ0(c, zm, zp) (zlo ? ((c).y - 1.5f * (c).x + 0.5f * (zp)) : ((c).y - (zm)))
#define DZ1(c, zm, zp) (zhi ? (1.5f * (c).y - (c).x - 0.5f * (zm)) : ((zp) - (c).x))
    float dz000 = DZ0(c00, zm00, zp00), dz001 = DZ1(c00, zm00, zp00);
    float dz010 = DZ0(c01, zm01, zp01), dz011 = DZ1(c01, zm01, zp01);
    float dz100 = DZ0(c10, zm10, zp10), dz101 = DZ1(c10, zm10, zp10);
    float dz110 = DZ0(c11, zm11, zp11), dz111 = DZ1(c11, zm11, zp11);

    // ---- y neighbors ----
    bool ylo = (by == 0), yhi = (by == 127);
    int ym = ylo ? y0 : y0 - 1;
    int yp = yhi ? y1 : y1 + 1;
    float2 m0 = __ldg(g2 + rowf2(x0, ym, bz));
    float2 m1 = __ldg(g2 + rowf2(x1, ym, bz));
    float2 p0 = __ldg(g2 + rowf2(x0, yp, bz));
    float2 p1 = __ldg(g2 + rowf2(x1, yp, bz));

#define DY0(c0, c1, m, p, k) (ylo ? ((c1).k - 1.5f * (c0).k + 0.5f * (p).k) : ((c1).k - (m).k))
#define DY1(c0, c1, m, p, k) (yhi ? (1.5f * (c1).k - (c0).k - 0.5f * (m).k) : ((p).k - (c0).k))
    float dy000 = DY0(c00, c01, m0, p0, x), dy001 = DY0(c00, c01, m0, p0, y);
    float dy010 = DY1(c00, c01, m0, p0, x), dy011 = DY1(c00, c01, m0, p0, y);
    float dy100 = DY0(c10, c11, m1, p1, x), dy101 = DY0(c10, c11, m1, p1, y);
    float dy110 = DY1(c10, c11, m1, p1, x), dy111 = DY1(c10, c11, m1, p1, y);

    // ---- x neighbors ----
    bool xlo = (bx == 0), xhi = (bx == 127);
    int xm = xlo ? x0 : x0 - 1;
    int xp = xhi ? x1 : x1 + 1;
    float2 a0 = __ldg(g2 + rowf2(xm, y0, bz));
    float2 a1 = __ldg(g2 + rowf2(xm, y1, bz));
    float2 b0 = __ldg(g2 + rowf2(xp, y0, bz));
    float2 b1 = __ldg(g2 + rowf2(xp, y1, bz));

#define DX0(c0, c1, a, b, k) (xlo ? ((c1).k - 1.5f * (c0).k + 0.5f * (b).k) : ((c1).k - (a).k))
#define DX1(c0, c1, a, b, k) (xhi ? (1.5f * (c1).k - (c0).k - 0.5f * (a).k) : ((b).k - (c0).k))
    float dx000 = DX0(c00, c10, a0, b0, x), dx001 = DX0(c00, c10, a0, b0, y);
    float dx010 = DX0(c01, c11, a1, b1, x), dx011 = DX0(c01, c11, a1, b1, y);
    float dx100 = DX1(c00, c10, a0, b0, x), dx101 = DX1(c00, c10, a0, b0, y);
    float dx110 = DX1(c01, c11, a1, b1, x), dx111 = DX1(c01, c11, a1, b1, y);

    const float S = 255.0f / 8.0f;   // 1/(2*VS)

    int brick = (((bx << 7) | by) << 7) | bz;
    float4* __restrict__ dst = reinterpret_cast<float4*>(g_table + ((long long)brick << 3));

    uint4 v;
    v.x = packh2(dx000 * S, dy000 * S);
    v.y = packh2(dz000 * S, fmaxf(-c00.x, 0.0f));
    v.z = packh2(dx001 * S, dy001 * S);
    v.w = packh2(dz001 * S, fmaxf(-c00.y, 0.0f));
    __stcs(dst + 0, *reinterpret_cast<float4*>(&v));

    v.x = packh2(dx010 * S, dy010 * S);
    v.y = packh2(dz010 * S, fmaxf(-c01.x, 0.0f));
    v.z = packh2(dx011 * S, dy011 * S);
    v.w = packh2(dz011 * S, fmaxf(-c01.y, 0.0f));
    __stcs(dst + 1, *reinterpret_cast<float4*>(&v));

    v.x = packh2(dx100 * S, dy100 * S);
    v.y = packh2(dz100 * S, fmaxf(-c10.x, 0.0f));
    v.z = packh2(dx101 * S, dy101 * S);
    v.w = packh2(dz101 * S, fmaxf(-c10.y, 0.0f));
    __stcs(dst + 2, *reinterpret_cast<float4*>(&v));

    v.x = packh2(dx110 * S, dy110 * S);
    v.y = packh2(dz110 * S, fmaxf(-c11.x, 0.0f));
    v.z = packh2(dx111 * S, dy111 * S);
    v.w = packh2(dz111 * S, fmaxf(-c11.y, 0.0f));
    __stcs(dst + 3, *reinterpret_cast<float4*>(&v));
}

__device__ __forceinline__ void corner_acc(uint2 v, float w,
                                           float& ax, float& ay, float& az) {
    __half2 h_xy = *reinterpret_cast<__half2*>(&v.x);
    __half2 h_zw = *reinterpret_cast<__half2*>(&v.y);
    float2 xy = __half22float2(h_xy);
    float2 zw = __half22float2(h_zw);
    ax = fmaf(w, xy.x, ax);
    ay = fmaf(w, xy.y, ay);
    az = fmaf(w, zw.x, az);
}

__global__ void __launch_bounds__(256)
gather_kernel(const int* __restrict__ vidx,
              const float* __restrict__ pos,
              const int* __restrict__ mask,
              float4* __restrict__ out,
              int npix) {
    int p = blockIdx.x * blockDim.x + threadIdx.x;
    if (p >= npix) return;

    const float BB_MIN_F = -2.0f;
    const float VS = 4.0f / 255.0f;

    int x = __ldcs(vidx + 3 * p + 0);
    int y = __ldcs(vidx + 3 * p + 1);
    int z = __ldcs(vidx + 3 * p + 2);

    float px = __ldcs(pos + 3 * p + 0);
    float py = __ldcs(pos + 3 * p + 1);
    float pz = __ldcs(pos + 3 * p + 2);

    float m = (float)__ldcs(mask + p);

    float tx = (px - (BB_MIN_F + (float)x * VS)) / VS;
    float ty = (py - (BB_MIN_F + (float)y * VS)) / VS;
    float tz = (pz - (BB_MIN_F + (float)z * VS)) / VS;

    int xp0 = ((x >> 1) << 17)       + ((x & 1) << 2);
    int xp1 = (((x + 1) >> 1) << 17) + (((x + 1) & 1) << 2);
    int yp0 = ((y >> 1) << 10)       + ((y & 1) << 1);
    int yp1 = (((y + 1) >> 1) << 10) + (((y + 1) & 1) << 1);
    int zp0 = ((z >> 1) << 3)        + (z & 1);
    int zp1 = (((z + 1) >> 1) << 3)  + ((z + 1) & 1);

    const uint2* __restrict__ T = g_table;

    uint2 c000 = __ldg(T + xp0 + yp0 + zp0);
    uint2 c001 = __ldg(T + xp0 + yp0 + zp1);
    uint2 c010 = __ldg(T + xp0 + yp1 + zp0);
    uint2 c011 = __ldg(T + xp0 + yp1 + zp1);
    uint2 c100 = __ldg(T + xp1 + yp0 + zp0);
    uint2 c101 = __ldg(T + xp1 + yp0 + zp1);
    uint2 c110 = __ldg(T + xp1 + yp1 + zp0);
    uint2 c111 = __ldg(T + xp1 + yp1 + zp1);

    float u0 = 1.0f - tx, u1 = tx;
    float v0 = 1.0f - ty, v1 = ty;
    float s0 = 1.0f - tz, s1 = tz;

    float w000 = u0 * v0 * s0;
    float w001 = u0 * v0 * s1;
    float w010 = u0 * v1 * s0;
    float w011 = u0 * v1 * s1;
    float w100 = u1 * v0 * s0;
    float w101 = u1 * v0 * s1;
    float w110 = u1 * v1 * s0;
    float w111 = u1 * v1 * s1;

    float inv = 1.0f - m;   // weights sum to 1

    float Nx = inv, Ny = inv, Nz = inv;
    corner_acc(c000, w000, Nx, Ny, Nz);
    corner_acc(c001, w001, Nx, Ny, Nz);
    corner_acc(c010, w010, Nx, Ny, Nz);
    corner_acc(c011, w011, Nx, Ny, Nz);
    corner_acc(c100, w100, Nx, Ny, Nz);
    corner_acc(c101, w101, Nx, Ny, Nz);
    corner_acc(c110, w110, Nx, Ny, Nz);
    corner_acc(c111, w111, Nx, Ny, Nz);

    __half2 h_zw = *reinterpret_cast<__half2*>(&c000.y);
    float gridx = __half2float(__high2half(h_zw)) * m;

    __stcs(out + p, make_float4(Nx, Ny, Nz, gridx));
}

extern "C" void kernel_launch(void* const* d_in, const int* in_sizes, int n_in,
                              void* d_out, int out_size) {
    const float* grid = (const float*)d_in[0];
    const int*   vidx = (const int*)d_in[1];
    const float* pos  = (const float*)d_in[2];
    // d_in[3] = voxel_min_point: unused (recomputed bit-identically)
    const int*   mask = (const int*)d_in[4];

    int npix = in_sizes[4];  // H*W

    precompute_normals_kernel<<<NVOX / 8 / 256, 256>>>(grid);

    int blocks = (npix + 255) / 256;
    gather_kernel<<<blocks, 256>>>(vidx, pos, mask, (float4*)d_out, npix);
}

// round 7
// speedup vs baseline: 1.3179x; 1.3179x over previous
#include <cuda_runtime.h>
#include <cuda_fp16.h>

// SDFGrid: trilinear-interpolated grid normals + relu(-grid) gather.
//
// R7: recombination of measured-best pieces:
//  - precompute: R4 brick-per-thread, PLAIN stores (46.5us measured; __stcs
//    variant regressed both kernels by evicting the table from L2).
//  - gather: R5 form with __ldcs pixel streams + __stcs output (49.6us).

#define GRID_R   256
#define NVOX     (GRID_R * GRID_R * GRID_R)

// Brick-swizzled: node (x,y,z) -> uint2 index
//   brick = ((x>>1)*128 + (y>>1))*128 + (z>>1)
//   idx   = brick*8 + (x&1)*4 + (y&1)*2 + (z&1)
static __device__ uint2 g_table[NVOX];

__device__ __forceinline__ unsigned int packh2(float a, float b) {
    __half2 h = __floats2half2_rn(a, b);
    return *reinterpret_cast<unsigned int*>(&h);
}

// float2 index of the z-pair (bz) of row (x, y)
__device__ __forceinline__ int rowf2(int x, int y, int bz) {
    return ((x << 8) + y) * 128 + bz;
}

// One thread = one 2x2x2 brick (8 nodes), 4 contiguous 16B stores.
__global__ void __launch_bounds__(256)
precompute_normals_kernel(const float* __restrict__ g) {
    int tid = blockIdx.x * blockDim.x + threadIdx.x;   // NVOX/8 threads
    int bz = tid & 127;
    int by = (tid >> 7) & 127;
    int bx = tid >> 14;

    int x0 = bx << 1, x1 = x0 + 1;
    int y0 = by << 1, y1 = y0 + 1;

    const float2* __restrict__ g2 = (const float2*)g;

    float2 c00 = __ldg(g2 + rowf2(x0, y0, bz));
    float2 c01 = __ldg(g2 + rowf2(x0, y1, bz));
    float2 c10 = __ldg(g2 + rowf2(x1, y0, bz));
    float2 c11 = __ldg(g2 + rowf2(x1, y1, bz));

    // ---- z neighbors: scalars at z0-1, z0+2 (clamped addr at borders) ----
    bool zlo = (bz == 0), zhi = (bz == 127);
    int dm = zlo ? 0 : -1;
    int dp = zhi ? 0 : 2;
    int e00 = rowf2(x0, y0, bz) * 2, e01 = rowf2(x0, y1, bz) * 2;
    int e10 = rowf2(x1, y0, bz) * 2, e11 = rowf2(x1, y1, bz) * 2;
    float zm00 = __ldg(g + e00 + dm), zp00 = __ldg(g + e00 + dp);
    float zm01 = __ldg(g + e01 + dm), zp01 = __ldg(g + e01 + dp);
    float zm10 = __ldg(g + e10 + dm), zp10 = __ldg(g + e10 + dp);
    float zm11 = __ldg(g + e11 + dm), zp11 = __ldg(g + e11 + dp);

#define DZ0(c, zm, zp) (zlo ? ((c).y - 1.5f * (c).x + 0.5f * (zp)) : ((c).y - (zm)))
#define DZ1(c, zm, zp) (zhi ? (1.5f * (c).y - (c).x - 0.5f * (zm)) : ((zp) - (c).x))
    float dz000 = DZ0(c00, zm00, zp00), dz001 = DZ1(c00, zm00, zp00);
    float dz010 = DZ0(c01, zm01, zp01), dz011 = DZ1(c01, zm01, zp01);
    float dz100 = DZ0(c10, zm10, zp10), dz101 = DZ1(c10, zm10, zp10);
    float dz110 = DZ0(c11, zm11, zp11), dz111 = DZ1(c11, zm11, zp11);

    // ---- y neighbors ----
    bool ylo = (by == 0), yhi = (by == 127);
    int ym = ylo ? y0 : y0 - 1;
    int yp = yhi ? y1 : y1 + 1;
    float2 m0 = __ldg(g2 + rowf2(x0, ym, bz));
    float2 m1 = __ldg(g2 + rowf2(x1, ym, bz));
    float2 p0 = __ldg(g2 + rowf2(x0, yp, bz));
    float2 p1 = __ldg(g2 + rowf2(x1, yp, bz));

#define DY0(c0, c1, m, p, k) (ylo ? ((c1).k - 1.5f * (c0).k + 0.5f * (p).k) : ((c1).k - (m).k))
#define DY1(c0, c1, m, p, k) (yhi ? (1.5f * (c1).k - (c0).k - 0.5f * (m).k) : ((p).k - (c0).k))
    float dy000 = DY0(c00, c01, m0, p0, x), dy001 = DY0(c00, c01, m0, p0, y);
    float dy010 = DY1(c00, c01, m0, p0, x), dy011 = DY1(c00, c01, m0, p0, y);
    float dy100 = DY0(c10, c11, m1, p1, x), dy101 = DY0(c10, c11, m1, p1, y);
    float dy110 = DY1(c10, c11, m1, p1, x), dy111 = DY1(c10, c11, m1, p1, y);

    // ---- x neighbors ----
    bool xlo = (bx == 0), xhi = (bx == 127);
    int xm = xlo ? x0 : x0 - 1;
    int xp = xhi ? x1 : x1 + 1;
    float2 a0 = __ldg(g2 + rowf2(xm, y0, bz));
    float2 a1 = __ldg(g2 + rowf2(xm, y1, bz));
    float2 b0 = __ldg(g2 + rowf2(xp, y0, bz));
    float2 b1 = __ldg(g2 + rowf2(xp, y1, bz));

#define DX0(c0, c1, a, b, k) (xlo ? ((c1).k - 1.5f * (c0).k + 0.5f * (b).k) : ((c1).k - (a).k))
#define DX1(c0, c1, a, b, k) (xhi ? (1.5f * (c1).k - (c0).k - 0.5f * (a).k) : ((b).k - (c0).k))
    float dx000 = DX0(c00, c10, a0, b0, x), dx001 = DX0(c00, c10, a0, b0, y);
    float dx010 = DX0(c01, c11, a1, b1, x), dx011 = DX0(c01, c11, a1, b1, y);
    float dx100 = DX1(c00, c10, a0, b0, x), dx101 = DX1(c00, c10, a0, b0, y);
    float dx110 = DX1(c01, c11, a1, b1, x), dx111 = DX1(c01, c11, a1, b1, y);

    const float S = 255.0f / 8.0f;   // 1/(2*VS)

    int brick = (((bx << 7) | by) << 7) | bz;
    uint2* __restrict__ dst = g_table + ((long long)brick << 3);

    uint4 v;
    v.x = packh2(dx000 * S, dy000 * S);
    v.y = packh2(dz000 * S, fmaxf(-c00.x, 0.0f));
    v.z = packh2(dx001 * S, dy001 * S);
    v.w = packh2(dz001 * S, fmaxf(-c00.y, 0.0f));
    *reinterpret_cast<uint4*>(dst + 0) = v;

    v.x = packh2(dx010 * S, dy010 * S);
    v.y = packh2(dz010 * S, fmaxf(-c01.x, 0.0f));
    v.z = packh2(dx011 * S, dy011 * S);
    v.w = packh2(dz011 * S, fmaxf(-c01.y, 0.0f));
    *reinterpret_cast<uint4*>(dst + 2) = v;

    v.x = packh2(dx100 * S, dy100 * S);
    v.y = packh2(dz100 * S, fmaxf(-c10.x, 0.0f));
    v.z = packh2(dx101 * S, dy101 * S);
    v.w = packh2(dz101 * S, fmaxf(-c10.y, 0.0f));
    *reinterpret_cast<uint4*>(dst + 4) = v;

    v.x = packh2(dx110 * S, dy110 * S);
    v.y = packh2(dz110 * S, fmaxf(-c11.x, 0.0f));
    v.z = packh2(dx111 * S, dy111 * S);
    v.w = packh2(dz111 * S, fmaxf(-c11.y, 0.0f));
    *reinterpret_cast<uint4*>(dst + 6) = v;
}

__device__ __forceinline__ void corner_acc(uint2 v, float w,
                                           float& ax, float& ay, float& az) {
    __half2 h_xy = *reinterpret_cast<__half2*>(&v.x);
    __half2 h_zw = *reinterpret_cast<__half2*>(&v.y);
    float2 xy = __half22float2(h_xy);
    float2 zw = __half22float2(h_zw);
    ax = fmaf(w, xy.x, ax);
    ay = fmaf(w, xy.y, ay);
    az = fmaf(w, zw.x, az);
}

__global__ void __launch_bounds__(256)
gather_kernel(const int* __restrict__ vidx,
              const float* __restrict__ pos,
              const int* __restrict__ mask,
              float4* __restrict__ out,
              int npix) {
    int p = blockIdx.x * blockDim.x + threadIdx.x;
    if (p >= npix) return;

    const float BB_MIN_F = -2.0f;
    const float VS = 4.0f / 255.0f;

    // Streaming inputs: evict-first so the table keeps L2.
    int x = __ldcs(vidx + 3 * p + 0);
    int y = __ldcs(vidx + 3 * p + 1);
    int z = __ldcs(vidx + 3 * p + 2);

    float px = __ldcs(pos + 3 * p + 0);
    float py = __ldcs(pos + 3 * p + 1);
    float pz = __ldcs(pos + 3 * p + 2);

    float m = (float)__ldcs(mask + p);

    float tx = (px - (BB_MIN_F + (float)x * VS)) / VS;
    float ty = (py - (BB_MIN_F + (float)y * VS)) / VS;
    float tz = (pz - (BB_MIN_F + (float)z * VS)) / VS;

    int xp0 = ((x >> 1) << 17)       + ((x & 1) << 2);
    int xp1 = (((x + 1) >> 1) << 17) + (((x + 1) & 1) << 2);
    int yp0 = ((y >> 1) << 10)       + ((y & 1) << 1);
    int yp1 = (((y + 1) >> 1) << 10) + (((y + 1) & 1) << 1);
    int zp0 = ((z >> 1) << 3)        + (z & 1);
    int zp1 = (((z + 1) >> 1) << 3)  + ((z + 1) & 1);

    const uint2* __restrict__ T = g_table;

    uint2 c000 = __ldg(T + xp0 + yp0 + zp0);
    uint2 c001 = __ldg(T + xp0 + yp0 + zp1);
    uint2 c010 = __ldg(T + xp0 + yp1 + zp0);
    uint2 c011 = __ldg(T + xp0 + yp1 + zp1);
    uint2 c100 = __ldg(T + xp1 + yp0 + zp0);
    uint2 c101 = __ldg(T + xp1 + yp0 + zp1);
    uint2 c110 = __ldg(T + xp1 + yp1 + zp0);
    uint2 c111 = __ldg(T + xp1 + yp1 + zp1);

    float u0 = 1.0f - tx, u1 = tx;
    float v0 = 1.0f - ty, v1 = ty;
    float s0 = 1.0f - tz, s1 = tz;

    float w000 = u0 * v0 * s0;
    float w001 = u0 * v0 * s1;
    float w010 = u0 * v1 * s0;
    float w011 = u0 * v1 * s1;
    float w100 = u1 * v0 * s0;
    float w101 = u1 * v0 * s1;
    float w110 = u1 * v1 * s0;
    float w111 = u1 * v1 * s1;

    float inv = 1.0f - m;   // weights sum to 1

    float Nx = inv, Ny = inv, Nz = inv;
    corner_acc(c000, w000, Nx, Ny, Nz);
    corner_acc(c001, w001, Nx, Ny, Nz);
    corner_acc(c010, w010, Nx, Ny, Nz);
    corner_acc(c011, w011, Nx, Ny, Nz);
    corner_acc(c100, w100, Nx, Ny, Nz);
    corner_acc(c101, w101, Nx, Ny, Nz);
    corner_acc(c110, w110, Nx, Ny, Nz);
    corner_acc(c111, w111, Nx, Ny, Nz);

    __half2 h_zw = *reinterpret_cast<__half2*>(&c000.y);
    float gridx = __half2float(__high2half(h_zw)) * m;

    __stcs(out + p, make_float4(Nx, Ny, Nz, gridx));
}

extern "C" void kernel_launch(void* const* d_in, const int* in_sizes, int n_in,
                              void* d_out, int out_size) {
    const float* grid = (const float*)d_in[0];
    const int*   vidx = (const int*)d_in[1];
    const float* pos  = (const float*)d_in[2];
    // d_in[3] = voxel_min_point: unused (recomputed bit-identically)
    const int*   mask = (const int*)d_in[4];

    int npix = in_sizes[4];  // H*W

    precompute_normals_kernel<<<NVOX / 8 / 256, 256>>>(grid);

    int blocks = (npix + 255) / 256;
    gather_kernel<<<blocks, 256>>>(vidx, pos, mask, (float4*)d_out, npix);
}

// round 9
// speedup vs baseline: 1.4398x; 1.0925x over previous
#include <cuda_runtime.h>
#include <cuda_fp16.h>

// SDFGrid: trilinear-interpolated grid normals + relu(-grid) gather.
//
// R8: precompute keeps R4's brick-per-thread compute but stages the 64B brick
// output in shared memory (swizzled, bank-conflict-free), then the block
// writes its contiguous 16KB table region with coalesced STG.128. This
// removes the ~128 partial-sector store wavefronts/warp of the direct
// 64B-lane-stride stores. Gather unchanged from R7.

#define GRID_R   256
#define NVOX     (GRID_R * GRID_R * GRID_R)

// Brick-swizzled: node (x,y,z) -> uint2 index
//   brick = ((x>>1)*128 + (y>>1))*128 + (z>>1)
//   idx   = brick*8 + (x&1)*4 + (y&1)*2 + (z&1)
static __device__ uint2 g_table[NVOX];

__device__ __forceinline__ unsigned int packh2(float a, float b) {
    __half2 h = __floats2half2_rn(a, b);
    return *reinterpret_cast<unsigned int*>(&h);
}

// float2 index of the z-pair (bz) of row (x, y)
__device__ __forceinline__ int rowf2(int x, int y, int bz) {
    return ((x << 8) + y) * 128 + bz;
}

// smem slot for (local thread t, chunk i): swizzle so that the writer's
// 64B-stride STS.128 is bank-conflict-free; reader stays conflict-free too.
__device__ __forceinline__ int smslot(int t, int i) {
    return t * 4 + ((i + (t >> 1)) & 3);
}

// One thread = one 2x2x2 brick (8 nodes); output staged via smem.
__global__ void __launch_bounds__(256)
precompute_normals_kernel(const float* __restrict__ g) {
    __shared__ uint4 sm[1024];   // 256 threads * 4 chunks * 16B = 16 KB

    int tid = blockIdx.x * blockDim.x + threadIdx.x;   // NVOX/8 threads
    int bz = tid & 127;
    int by = (tid >> 7) & 127;
    int bx = tid >> 14;

    int x0 = bx << 1, x1 = x0 + 1;
    int y0 = by << 1, y1 = y0 + 1;

    const float2* __restrict__ g2 = (const float2*)g;

    float2 c00 = __ldg(g2 + rowf2(x0, y0, bz));
    float2 c01 = __ldg(g2 + rowf2(x0, y1, bz));
    float2 c10 = __ldg(g2 + rowf2(x1, y0, bz));
    float2 c11 = __ldg(g2 + rowf2(x1, y1, bz));

    // ---- z neighbors: scalars at z0-1, z0+2 (clamped addr at borders) ----
    bool zlo = (bz == 0), zhi = (bz == 127);
    int dm = zlo ? 0 : -1;
    int dp = zhi ? 0 : 2;
    int e00 = rowf2(x0, y0, bz) * 2, e01 = rowf2(x0, y1, bz) * 2;
    int e10 = rowf2(x1, y0, bz) * 2, e11 = rowf2(x1, y1, bz) * 2;
    float zm00 = __ldg(g + e00 + dm), zp00 = __ldg(g + e00 + dp);
    float zm01 = __ldg(g + e01 + dm), zp01 = __ldg(g + e01 + dp);
    float zm10 = __ldg(g + e10 + dm), zp10 = __ldg(g + e10 + dp);
    float zm11 = __ldg(g + e11 + dm), zp11 = __ldg(g + e11 + dp);

#define DZ0(c, zm, zp) (zlo ? ((c).y - 1.5f * (c).x + 0.5f * (zp)) : ((c).y - (zm)))
#define DZ1(c, zm, zp) (zhi ? (1.5f * (c).y - (c).x - 0.5f * (zm)) : ((zp) - (c).x))
    float dz000 = DZ0(c00, zm00, zp00), dz001 = DZ1(c00, zm00, zp00);
    float dz010 = DZ0(c01, zm01, zp01), dz011 = DZ1(c01, zm01, zp01);
    float dz100 = DZ0(c10, zm10, zp10), dz101 = DZ1(c10, zm10, zp10);
    float dz110 = DZ0(c11, zm11, zp11), dz111 = DZ1(c11, zm11, zp11);

    // ---- y neighbors ----
    bool ylo = (by == 0), yhi = (by == 127);
    int ym = ylo ? y0 : y0 - 1;
    int yp = yhi ? y1 : y1 + 1;
    float2 m0 = __ldg(g2 + rowf2(x0, ym, bz));
    float2 m1 = __ldg(g2 + rowf2(x1, ym, bz));
    float2 p0 = __ldg(g2 + rowf2(x0, yp, bz));
    float2 p1 = __ldg(g2 + rowf2(x1, yp, bz));

#define DY0(c0, c1, m, p, k) (ylo ? ((c1).k - 1.5f * (c0).k + 0.5f * (p).k) : ((c1).k - (m).k))
#define DY1(c0, c1, m, p, k) (yhi ? (1.5f * (c1).k - (c0).k - 0.5f * (m).k) : ((p).k - (c0).k))
    float dy000 = DY0(c00, c01, m0, p0, x), dy001 = DY0(c00, c01, m0, p0, y);
    float dy010 = DY1(c00, c01, m0, p0, x), dy011 = DY1(c00, c01, m0, p0, y);
    float dy100 = DY0(c10, c11, m1, p1, x), dy101 = DY0(c10, c11, m1, p1, y);
    float dy110 = DY1(c10, c11, m1, p1, x), dy111 = DY1(c10, c11, m1, p1, y);

    // ---- x neighbors ----
    bool xlo = (bx == 0), xhi = (bx == 127);
    int xm = xlo ? x0 : x0 - 1;
    int xp = xhi ? x1 : x1 + 1;
    float2 a0 = __ldg(g2 + rowf2(xm, y0, bz));
    float2 a1 = __ldg(g2 + rowf2(xm, y1, bz));
    float2 b0 = __ldg(g2 + rowf2(xp, y0, bz));
    float2 b1 = __ldg(g2 + rowf2(xp, y1, bz));

#define DX0(c0, c1, a, b, k) (xlo ? ((c1).k - 1.5f * (c0).k + 0.5f * (b).k) : ((c1).k - (a).k))
#define DX1(c0, c1, a, b, k) (xhi ? (1.5f * (c1).k - (c0).k - 0.5f * (a).k) : ((b).k - (c0).k))
    float dx000 = DX0(c00, c10, a0, b0, x), dx001 = DX0(c00, c10, a0, b0, y);
    float dx010 = DX0(c01, c11, a1, b1, x), dx011 = DX0(c01, c11, a1, b1, y);
    float dx100 = DX1(c00, c10, a0, b0, x), dx101 = DX1(c00, c10, a0, b0, y);
    float dx110 = DX1(c01, c11, a1, b1, x), dx111 = DX1(c01, c11, a1, b1, y);

    const float S = 255.0f / 8.0f;   // 1/(2*VS)

    int t = threadIdx.x;
    uint4 v;
    // chunk 0: (ox=0, oy=0), oz = 0,1
    v.x = packh2(dx000 * S, dy000 * S);
    v.y = packh2(dz000 * S, fmaxf(-c00.x, 0.0f));
    v.z = packh2(dx001 * S, dy001 * S);
    v.w = packh2(dz001 * S, fmaxf(-c00.y, 0.0f));
    sm[smslot(t, 0)] = v;
    // chunk 1: (ox=0, oy=1)
    v.x = packh2(dx010 * S, dy010 * S);
    v.y = packh2(dz010 * S, fmaxf(-c01.x, 0.0f));
    v.z = packh2(dx011 * S, dy011 * S);
    v.w = packh2(dz011 * S, fmaxf(-c01.y, 0.0f));
    sm[smslot(t, 1)] = v;
    // chunk 2: (ox=1, oy=0)
    v.x = packh2(dx100 * S, dy100 * S);
    v.y = packh2(dz100 * S, fmaxf(-c10.x, 0.0f));
    v.z = packh2(dx101 * S, dy101 * S);
    v.w = packh2(dz101 * S, fmaxf(-c10.y, 0.0f));
    sm[smslot(t, 2)] = v;
    // chunk 3: (ox=1, oy=1)
    v.x = packh2(dx110 * S, dy110 * S);
    v.y = packh2(dz110 * S, fmaxf(-c11.x, 0.0f));
    v.z = packh2(dx111 * S, dy111 * S);
    v.w = packh2(dz111 * S, fmaxf(-c11.y, 0.0f));
    sm[smslot(t, 3)] = v;

    __syncthreads();

    // Coalesced copy-out: block's table region is 1024 contiguous uint4 chunks.
    uint4* __restrict__ gdst = reinterpret_cast<uint4*>(g_table) + (long long)blockIdx.x * 1024;
#pragma unroll
    for (int k = 0; k < 4; k++) {
        int e = t + 256 * k;            // gmem-linear chunk index within block
        int pt = e >> 2;                // producing thread
        int pi = e & 3;                 // its chunk
        gdst[e] = sm[smslot(pt, pi)];
    }
}

__device__ __forceinline__ void corner_acc(uint2 v, float w,
                                           float& ax, float& ay, float& az) {
    __half2 h_xy = *reinterpret_cast<__half2*>(&v.x);
    __half2 h_zw = *reinterpret_cast<__half2*>(&v.y);
    float2 xy = __half22float2(h_xy);
    float2 zw = __half22float2(h_zw);
    ax = fmaf(w, xy.x, ax);
    ay = fmaf(w, xy.y, ay);
    az = fmaf(w, zw.x, az);
}

__global__ void __launch_bounds__(256)
gather_kernel(const int* __restrict__ vidx,
              const float* __restrict__ pos,
              const int* __restrict__ mask,
              float4* __restrict__ out,
              int npix) {
    int p = blockIdx.x * blockDim.x + threadIdx.x;
    if (p >= npix) return;

    const float BB_MIN_F = -2.0f;
    const float VS = 4.0f / 255.0f;

    // Streaming inputs: evict-first so the table keeps L2.
    int x = __ldcs(vidx + 3 * p + 0);
    int y = __ldcs(vidx + 3 * p + 1);
    int z = __ldcs(vidx + 3 * p + 2);

    float px = __ldcs(pos + 3 * p + 0);
    float py = __ldcs(pos + 3 * p + 1);
    float pz = __ldcs(pos + 3 * p + 2);

    float m = (float)__ldcs(mask + p);

    float tx = (px - (BB_MIN_F + (float)x * VS)) / VS;
    float ty = (py - (BB_MIN_F + (float)y * VS)) / VS;
    float tz = (pz - (BB_MIN_F + (float)z * VS)) / VS;

    int xp0 = ((x >> 1) << 17)       + ((x & 1) << 2);
    int xp1 = (((x + 1) >> 1) << 17) + (((x + 1) & 1) << 2);
    int yp0 = ((y >> 1) << 10)       + ((y & 1) << 1);
    int yp1 = (((y + 1) >> 1) << 10) + (((y + 1) & 1) << 1);
    int zp0 = ((z >> 1) << 3)        + (z & 1);
    int zp1 = (((z + 1) >> 1) << 3)  + ((z + 1) & 1);

    const uint2* __restrict__ T = g_table;

    uint2 c000 = __ldg(T + xp0 + yp0 + zp0);
    uint2 c001 = __ldg(T + xp0 + yp0 + zp1);
    uint2 c010 = __ldg(T + xp0 + yp1 + zp0);
    uint2 c011 = __ldg(T + xp0 + yp1 + zp1);
    uint2 c100 = __ldg(T + xp1 + yp0 + zp0);
    uint2 c101 = __ldg(T + xp1 + yp0 + zp1);
    uint2 c110 = __ldg(T + xp1 + yp1 + zp0);
    uint2 c111 = __ldg(T + xp1 + yp1 + zp1);

    float u0 = 1.0f - tx, u1 = tx;
    float v0 = 1.0f - ty, v1 = ty;
    float s0 = 1.0f - tz, s1 = tz;

    float w000 = u0 * v0 * s0;
    float w001 = u0 * v0 * s1;
    float w010 = u0 * v1 * s0;
    float w011 = u0 * v1 * s1;
    float w100 = u1 * v0 * s0;
    float w101 = u1 * v0 * s1;
    float w110 = u1 * v1 * s0;
    float w111 = u1 * v1 * s1;

    float inv = 1.0f - m;   // weights sum to 1

    float Nx = inv, Ny = inv, Nz = inv;
    corner_acc(c000, w000, Nx, Ny, Nz);
    corner_acc(c001, w001, Nx, Ny, Nz);
    corner_acc(c010, w010, Nx, Ny, Nz);
    corner_acc(c011, w011, Nx, Ny, Nz);
    corner_acc(c100, w100, Nx, Ny, Nz);
    corner_acc(c101, w101, Nx, Ny, Nz);
    corner_acc(c110, w110, Nx, Ny, Nz);
    corner_acc(c111, w111, Nx, Ny, Nz);

    __half2 h_zw = *reinterpret_cast<__half2*>(&c000.y);
    float gridx = __half2float(__high2half(h_zw)) * m;

    __stcs(out + p, make_float4(Nx, Ny, Nz, gridx));
}

extern "C" void kernel_launch(void* const* d_in, const int* in_sizes, int n_in,
                              void* d_out, int out_size) {
    const float* grid = (const float*)d_in[0];
    const int*   vidx = (const int*)d_in[1];
    const float* pos  = (const float*)d_in[2];
    // d_in[3] = voxel_min_point: unused (recomputed bit-identically)
    const int*   mask = (const int*)d_in[4];

    int npix = in_sizes[4];  // H*W

    precompute_normals_kernel<<<NVOX / 8 / 256, 256>>>(grid);

    int blocks = (npix + 255) / 256;
    gather_kernel<<<blocks, 256>>>(vidx, pos, mask, (float4*)d_out, npix);
}